// round 2
// baseline (speedup 1.0000x reference)
#include <cuda_runtime.h>
#include <cstdint>
#include <cstddef>

#define NN   65536
#define F    512
#define KNN  16

#define BM   128
#define BN   64
#define BK   32
#define APAD 4

// Scratch (allocation-free rule: __device__ globals)
__device__ float g_htheta[(size_t)NN * F];
__device__ float g_hdst[(size_t)NN * F];
__device__ int   g_idx_is64;

// ---------------------------------------------------------------------------
// Index-width detection: int64 little-endian with values < 2^16 has every
// odd 32-bit word == 0. Random int32 indices fail this with p ~ 65536^-256.
// ---------------------------------------------------------------------------
__global__ void detect_idx_kernel(const unsigned int* __restrict__ w)
{
    int is64 = 1;
    for (int i = 1; i < 512; i += 2)
        if (w[i] != 0u) { is64 = 0; break; }
    g_idx_is64 = is64;
}

// ---------------------------------------------------------------------------
// Dual GEMM: C1 = A @ Wt, C2 = A @ Wp  (A: [NN,F], W: [F,F] row-major)
// Each block: 128 rows x 64 cols of BOTH outputs (A tile loaded once).
// Epilogue: g_htheta = C1 ; g_hdst = C2 - C1.
// ---------------------------------------------------------------------------
__global__ __launch_bounds__(256) void dual_gemm_kernel(
    const float* __restrict__ A,
    const float* __restrict__ Wt,
    const float* __restrict__ Wp)
{
    __shared__ float As[BK][BM + APAD];
    __shared__ float Bt[BK][BN];
    __shared__ float Bp[BK][BN];

    const int tid = threadIdx.x;
    const int m0  = blockIdx.y * BM;
    const int n0  = blockIdx.x * BN;

    const int arow = tid >> 3;      // 0..31
    const int af4  = tid & 7;       // 0..7
    const int brow = tid >> 4;      // 0..15
    const int bf4  = tid & 15;      // 0..15

    const int ty = tid >> 4;        // 0..15
    const int tx = tid & 15;        // 0..15

    float acc1[8][4];
    float acc2[8][4];
#pragma unroll
    for (int i = 0; i < 8; i++)
#pragma unroll
        for (int j = 0; j < 4; j++) { acc1[i][j] = 0.f; acc2[i][j] = 0.f; }

    for (int k0 = 0; k0 < F; k0 += BK) {
#pragma unroll
        for (int p = 0; p < 4; p++) {
            int r = arow + 32 * p;
            const float4 v = *reinterpret_cast<const float4*>(
                A + (size_t)(m0 + r) * F + k0 + af4 * 4);
            As[af4 * 4 + 0][r] = v.x;
            As[af4 * 4 + 1][r] = v.y;
            As[af4 * 4 + 2][r] = v.z;
            As[af4 * 4 + 3][r] = v.w;
        }
#pragma unroll
        for (int p = 0; p < 2; p++) {
            int r = brow + 16 * p;
            const float4 vt = *reinterpret_cast<const float4*>(
                Wt + (size_t)(k0 + r) * F + n0 + bf4 * 4);
            const float4 vp = *reinterpret_cast<const float4*>(
                Wp + (size_t)(k0 + r) * F + n0 + bf4 * 4);
            *reinterpret_cast<float4*>(&Bt[r][bf4 * 4]) = vt;
            *reinterpret_cast<float4*>(&Bp[r][bf4 * 4]) = vp;
        }
        __syncthreads();

#pragma unroll
        for (int kk = 0; kk < BK; kk++) {
            float a[8], bt[4], bp[4];
            *reinterpret_cast<float4*>(&a[0]) =
                *reinterpret_cast<const float4*>(&As[kk][ty * 8]);
            *reinterpret_cast<float4*>(&a[4]) =
                *reinterpret_cast<const float4*>(&As[kk][ty * 8 + 4]);
            *reinterpret_cast<float4*>(&bt[0]) =
                *reinterpret_cast<const float4*>(&Bt[kk][tx * 4]);
            *reinterpret_cast<float4*>(&bp[0]) =
                *reinterpret_cast<const float4*>(&Bp[kk][tx * 4]);
#pragma unroll
            for (int i = 0; i < 8; i++) {
#pragma unroll
                for (int j = 0; j < 4; j++) {
                    acc1[i][j] += a[i] * bt[j];
                    acc2[i][j] += a[i] * bp[j];
                }
            }
        }
        __syncthreads();
    }

#pragma unroll
    for (int i = 0; i < 8; i++) {
        const int m = m0 + ty * 8 + i;
        float* ht = &g_htheta[(size_t)m * F + n0 + tx * 4];
        float* hd = &g_hdst  [(size_t)m * F + n0 + tx * 4];
        float4 v1, v2;
        v1.x = acc1[i][0]; v1.y = acc1[i][1]; v1.z = acc1[i][2]; v1.w = acc1[i][3];
        v2.x = acc2[i][0] - acc1[i][0];
        v2.y = acc2[i][1] - acc1[i][1];
        v2.z = acc2[i][2] - acc1[i][2];
        v2.w = acc2[i][3] - acc1[i][3];
        *reinterpret_cast<float4*>(ht) = v1;
        *reinterpret_cast<float4*>(hd) = v2;
    }
}

// ---------------------------------------------------------------------------
// Gather + max + add: out[n,:] = max_{j<16} htheta[src[n,j],:] + hdst[n,:]
// One block (128 threads) per node; each thread handles one float4.
// ---------------------------------------------------------------------------
__global__ __launch_bounds__(128) void gather_max_kernel(
    const void* __restrict__ src,
    float* __restrict__ out)
{
    const int n  = blockIdx.x;
    const int c4 = threadIdx.x;   // 0..127

    __shared__ unsigned int sidx[KNN];
    if (threadIdx.x == 0) {
        const int is64 = g_idx_is64;
        if (is64) {
            const unsigned long long* s64 =
                (const unsigned long long*)src + (size_t)n * KNN;
            for (int j = 0; j < KNN; j++)
                sidx[j] = (unsigned int)s64[j] & 0xFFFFu;
        } else {
            const unsigned int* s32 =
                (const unsigned int*)src + (size_t)n * KNN;
            for (int j = 0; j < KNN; j++)
                sidx[j] = s32[j] & 0xFFFFu;
        }
    }
    __syncthreads();

    const float4* __restrict__ ht4 = reinterpret_cast<const float4*>(g_htheta);
    const float4* __restrict__ hd4 = reinterpret_cast<const float4*>(g_hdst);

    float4 m = ht4[(size_t)sidx[0] * (F / 4) + c4];
#pragma unroll
    for (int j = 1; j < KNN; j++) {
        const float4 v = ht4[(size_t)sidx[j] * (F / 4) + c4];
        m.x = fmaxf(m.x, v.x);
        m.y = fmaxf(m.y, v.y);
        m.z = fmaxf(m.z, v.z);
        m.w = fmaxf(m.w, v.w);
    }

    const float4 d = hd4[(size_t)n * (F / 4) + c4];
    float4 r;
    r.x = m.x + d.x; r.y = m.y + d.y; r.z = m.z + d.z; r.w = m.w + d.w;
    reinterpret_cast<float4*>(out)[(size_t)n * (F / 4) + c4] = r;
}

// ---------------------------------------------------------------------------
extern "C" void kernel_launch(void* const* d_in, const int* in_sizes, int n_in,
                              void* d_out, int out_size)
{
    const void*  src  = nullptr;
    const float* feat = nullptr;
    const float* Wt   = nullptr;
    const float* Wp   = nullptr;

    for (int i = 0; i < n_in; i++) {
        const int s = in_sizes[i];
        if (s == NN * KNN)      src  = d_in[i];
        else if (s == NN * F)   feat = (const float*)d_in[i];
        else if (s == F * F) {
            if (!Wt) Wt = (const float*)d_in[i];
            else     Wp = (const float*)d_in[i];
        }
    }

    detect_idx_kernel<<<1, 1>>>((const unsigned int*)src);

    dim3 gemm_grid(F / BN, NN / BM);            // (8, 512)
    dual_gemm_kernel<<<gemm_grid, 256>>>(feat, Wt, Wp);

    gather_max_kernel<<<NN, 128>>>(src, (float*)d_out);
}

// round 4
// speedup vs baseline: 2.7169x; 2.7169x over previous
#include <cuda_runtime.h>
#include <cuda_bf16.h>
#include <cstdint>
#include <cstddef>

#define NN   65536
#define F    512
#define KNN  16
#define NOUT 1024     // theta | phi concatenated columns
#define KEXT 1536     // 3 * F : hi*hi, hi*lo, lo*hi

#define BM 128
#define BN 128
#define BK 32
#define STAGES 3
#define GEMM_THREADS 256
#define NKTILES (KEXT / BK)        // 48

// padded smem row: 32 bf16 data + 8 pad = 40 bf16 = 80B (16B aligned, ldmatrix conflict-free)
#define ROWB 80
#define TILE_BYTES (128 * ROWB)    // 10240
#define STAGE_BYTES (2 * TILE_BYTES)
#define SM_TOTAL (STAGES * STAGE_BYTES)   // 61440

// ---------------- scratch (__device__ globals per allocation rules) --------
__device__ __align__(1024) float          g_hcat[(size_t)NN * NOUT];   // 256MB
__device__ __align__(1024) __nv_bfloat16  g_Ahi[(size_t)NN * F];       // 64MB
__device__ __align__(1024) __nv_bfloat16  g_Alo[(size_t)NN * F];       // 64MB
__device__ __align__(1024) __nv_bfloat16  g_BT[(size_t)NOUT * KEXT];   // 3MB
__device__ int g_idx_is64;

// ---------------- helpers ---------------------------------------------------
__device__ __forceinline__ uint32_t smem_to_u32(const void* p) {
    uint32_t a;
    asm("{ .reg .u64 t; cvta.to.shared.u64 t, %1; cvt.u32.u64 %0, t; }"
        : "=r"(a) : "l"(p));
    return a;
}
__device__ __forceinline__ void cp16(uint32_t dst, const void* src) {
    asm volatile("cp.async.cg.shared.global [%0], [%1], 16;" :: "r"(dst), "l"(src));
}
__device__ __forceinline__ void ldmatrix_x4(uint32_t* r, uint32_t addr) {
    asm volatile("ldmatrix.sync.aligned.m8n8.x4.shared.b16 {%0,%1,%2,%3}, [%4];"
                 : "=r"(r[0]), "=r"(r[1]), "=r"(r[2]), "=r"(r[3]) : "r"(addr));
}
__device__ __forceinline__ void mma_bf16(float* c, const uint32_t* a, const uint32_t* b) {
    asm volatile(
        "mma.sync.aligned.m16n8k16.row.col.f32.bf16.bf16.f32 "
        "{%0,%1,%2,%3}, {%4,%5,%6,%7}, {%8,%9}, {%0,%1,%2,%3};"
        : "+f"(c[0]), "+f"(c[1]), "+f"(c[2]), "+f"(c[3])
        : "r"(a[0]), "r"(a[1]), "r"(a[2]), "r"(a[3]), "r"(b[0]), "r"(b[1]));
}

// ---------------- index width detection -----------------------------------
__global__ void detect_idx_kernel(const unsigned int* __restrict__ w) {
    int is64 = 1;
    for (int i = 1; i < 512; i += 2)
        if (w[i] != 0u) { is64 = 0; break; }
    g_idx_is64 = is64;
}

// ---------------- feat -> (hi, lo) bf16 split ------------------------------
__global__ __launch_bounds__(256) void convert_A_kernel(const float* __restrict__ A) {
    const size_t i = (size_t)blockIdx.x * 256 + threadIdx.x;   // per float4
    const float4 v = reinterpret_cast<const float4*>(A)[i];
    float f[4] = {v.x, v.y, v.z, v.w};
    __nv_bfloat16 h[4], l[4];
#pragma unroll
    for (int j = 0; j < 4; j++) {
        h[j] = __float2bfloat16_rn(f[j]);
        l[j] = __float2bfloat16_rn(f[j] - __bfloat162float(h[j]));
    }
    reinterpret_cast<uint2*>(g_Ahi)[i] = *reinterpret_cast<uint2*>(h);
    reinterpret_cast<uint2*>(g_Alo)[i] = *reinterpret_cast<uint2*>(l);
}

// ---------------- W -> B_ext^T [NOUT][KEXT] bf16 ---------------------------
// row n of BT: [0,512): hi(W[k][n]) ; [512,1024): lo(W[k][n]) ; [1024,1536): hi(W[k][n])
__global__ __launch_bounds__(256) void convert_W_kernel(const float* __restrict__ Wt,
                                                        const float* __restrict__ Wp) {
    const int idx = blockIdx.x * 256 + threadIdx.x;   // [0, 1024*512)
    const int n = idx >> 9;
    const int k = idx & 511;
    const float* W = (n < 512) ? Wt : Wp;
    const int nc = n & 511;
    const float w = W[(size_t)k * 512 + nc];
    const __nv_bfloat16 hi = __float2bfloat16_rn(w);
    const __nv_bfloat16 lo = __float2bfloat16_rn(w - __bfloat162float(hi));
    __nv_bfloat16* row = g_BT + (size_t)n * KEXT;
    row[k]        = hi;
    row[512 + k]  = lo;
    row[1024 + k] = hi;
}

// ---------------- HMMA dual GEMM -------------------------------------------
// C[65536 x 1024] = A_ext[65536 x 1536] @ B_ext[1536 x 1024]
// A_ext k-chunk: [0,512) Ahi | [512,1024) Ahi | [1024,1536) Alo
// (pairs with BT chunks hi | lo | hi -> hi*hi + hi*lo + lo*hi)
__device__ __forceinline__ void load_tile(uint32_t sm_base, int stage, int t,
                                          int m0, int n0, int tid) {
    const int kc = t * BK;
    const __nv_bfloat16* abase = (kc < 1024) ? g_Ahi : g_Alo;
    const int klocal = kc & 511;
    const uint32_t smA = sm_base + stage * STAGE_BYTES;
    const uint32_t smB = smA + TILE_BYTES;
#pragma unroll
    for (int i = 0; i < 2; i++) {
        const int q = tid + i * GEMM_THREADS;   // 0..511
        const int r = q >> 2;                   // row 0..127
        const int c = q & 3;                    // 16B chunk
        cp16(smA + r * ROWB + c * 16,
             abase + (size_t)(m0 + r) * F + klocal + c * 8);
    }
#pragma unroll
    for (int i = 0; i < 2; i++) {
        const int q = tid + i * GEMM_THREADS;
        const int r = q >> 2;
        const int c = q & 3;
        cp16(smB + r * ROWB + c * 16,
             g_BT + (size_t)(n0 + r) * KEXT + kc + c * 8);
    }
    asm volatile("cp.async.commit_group;" ::: "memory");
}

__global__ __launch_bounds__(GEMM_THREADS, 2) void gemm_kernel() {
    extern __shared__ __align__(128) char smem[];
    const uint32_t sm_base = smem_to_u32(smem);
    const int tid = threadIdx.x;
    const int wid = tid >> 5;
    const int lid = tid & 31;

    // block swizzle: groups of 32 m-blocks sweep all 8 n-blocks (A stays in L2)
    const int bid   = blockIdx.x;
    const int group = bid >> 8;
    const int inner = bid & 255;
    const int n_blk = inner >> 5;
    const int m_blk = (group << 5) | (inner & 31);
    const int m0 = m_blk * BM;
    const int n0 = n_blk * BN;

    // warp layout: 4 (m) x 2 (n); warp tile 32m x 64n
    const int wm0 = (wid >> 1) * 32;
    const int wn0 = (wid & 1) * 64;

    float acc[2][8][4];
#pragma unroll
    for (int i = 0; i < 2; i++)
#pragma unroll
        for (int j = 0; j < 8; j++)
#pragma unroll
            for (int q = 0; q < 4; q++) acc[i][j][q] = 0.f;

    // prologue
    load_tile(sm_base, 0, 0, m0, n0, tid);
    load_tile(sm_base, 1, 1, m0, n0, tid);

    // ldmatrix lane addressing (within tile):
    //  A (mfrag i, kstep ks): row = wm0 + i*16 + (lid&15), col = ks*16 + (lid>>4)*8
    //  B (nfrag-pair j2, ks): row = wn0 + j2*16 + ((lid&16)?8:0) + (lid&7),
    //                         col = ks*16 + ((lid&8)?8:0)
    const int a_row_off = wm0 + (lid & 15);
    const int a_col_off = (lid >> 4) * 8;
    const int b_row_off = wn0 + ((lid & 16) >> 1) + (lid & 7);
    const int b_col_off = ((lid & 8) ? 8 : 0);

    for (int t = 0; t < NKTILES; t++) {
        const int st = t % STAGES;
        if (t + 1 < NKTILES) asm volatile("cp.async.wait_group 1;" ::: "memory");
        else                 asm volatile("cp.async.wait_group 0;" ::: "memory");
        __syncthreads();

        if (t + 2 < NKTILES)
            load_tile(sm_base, (t + 2) % STAGES, t + 2, m0, n0, tid);

        const uint32_t smA = sm_base + st * STAGE_BYTES;
        const uint32_t smB = smA + TILE_BYTES;

#pragma unroll
        for (int ks = 0; ks < 2; ks++) {
            uint32_t a[2][4], b[8][2];
#pragma unroll
            for (int i = 0; i < 2; i++)
                ldmatrix_x4(a[i], smA + (a_row_off + i * 16) * ROWB
                                      + (ks * 16 + a_col_off) * 2);
#pragma unroll
            for (int j2 = 0; j2 < 4; j2++) {
                uint32_t r[4];
                ldmatrix_x4(r, smB + (b_row_off + j2 * 16) * ROWB
                                   + (ks * 16 + b_col_off) * 2);
                b[j2 * 2 + 0][0] = r[0]; b[j2 * 2 + 0][1] = r[1];
                b[j2 * 2 + 1][0] = r[2]; b[j2 * 2 + 1][1] = r[3];
            }
#pragma unroll
            for (int i = 0; i < 2; i++)
#pragma unroll
                for (int j = 0; j < 8; j++)
                    mma_bf16(acc[i][j], a[i], b[j]);
        }
    }

    // epilogue: thread t of warp holds C[m + t/4 (+8)][n + 2*(t%4) (+1)]
    const int er = lid >> 2;
    const int ec = (lid & 3) * 2;
#pragma unroll
    for (int i = 0; i < 2; i++) {
#pragma unroll
        for (int j = 0; j < 8; j++) {
            const int m = m0 + wm0 + i * 16 + er;
            const int n = n0 + wn0 + j * 8 + ec;
            float2 v0 = make_float2(acc[i][j][0], acc[i][j][1]);
            float2 v1 = make_float2(acc[i][j][2], acc[i][j][3]);
            *reinterpret_cast<float2*>(&g_hcat[(size_t)m * NOUT + n])       = v0;
            *reinterpret_cast<float2*>(&g_hcat[(size_t)(m + 8) * NOUT + n]) = v1;
        }
    }
}

// ---------------- gather + max + add ---------------------------------------
// out[n][c] = max_j hcat[src[n][j]][c] + (hcat[n][512+c] - hcat[n][c])
__global__ __launch_bounds__(128) void gather_max_kernel(
    const void* __restrict__ src, float* __restrict__ out)
{
    const int n  = blockIdx.x;
    const int c4 = threadIdx.x;            // float4 lane, 0..127 (theta half)

    __shared__ unsigned int sidx[KNN];
    if (threadIdx.x == 0) {
        if (g_idx_is64) {
            const unsigned long long* s64 =
                (const unsigned long long*)src + (size_t)n * KNN;
            for (int j = 0; j < KNN; j++) sidx[j] = (unsigned int)s64[j] & 0xFFFFu;
        } else {
            const unsigned int* s32 = (const unsigned int*)src + (size_t)n * KNN;
            for (int j = 0; j < KNN; j++) sidx[j] = s32[j] & 0xFFFFu;
        }
    }
    __syncthreads();

    const float4* __restrict__ h4 = reinterpret_cast<const float4*>(g_hcat);

    float4 m = h4[(size_t)sidx[0] * (NOUT / 4) + c4];
#pragma unroll
    for (int j = 1; j < KNN; j++) {
        const float4 v = h4[(size_t)sidx[j] * (NOUT / 4) + c4];
        m.x = fmaxf(m.x, v.x); m.y = fmaxf(m.y, v.y);
        m.z = fmaxf(m.z, v.z); m.w = fmaxf(m.w, v.w);
    }
    const float4 th = h4[(size_t)n * (NOUT / 4) + c4];
    const float4 ph = h4[(size_t)n * (NOUT / 4) + 128 + c4];
    float4 r;
    r.x = m.x + ph.x - th.x; r.y = m.y + ph.y - th.y;
    r.z = m.z + ph.z - th.z; r.w = m.w + ph.w - th.w;
    reinterpret_cast<float4*>(out)[(size_t)n * (F / 4) + c4] = r;
}

// ---------------------------------------------------------------------------
extern "C" void kernel_launch(void* const* d_in, const int* in_sizes, int n_in,
                              void* d_out, int out_size)
{
    const void*  src  = nullptr;
    const float* feat = nullptr;
    const float* Wt   = nullptr;
    const float* Wp   = nullptr;

    for (int i = 0; i < n_in; i++) {
        const int s = in_sizes[i];
        if (s == NN * KNN)      src  = d_in[i];
        else if (s == NN * F)   feat = (const float*)d_in[i];
        else if (s == F * F) {
            if (!Wt) Wt = (const float*)d_in[i];
            else     Wp = (const float*)d_in[i];
        }
    }

    cudaFuncSetAttribute(gemm_kernel,
                         cudaFuncAttributeMaxDynamicSharedMemorySize, SM_TOTAL);

    detect_idx_kernel<<<1, 1>>>((const unsigned int*)src);
    convert_A_kernel<<<(NN * (F / 4)) / 256, 256>>>(feat);
    convert_W_kernel<<<(NOUT * F) / 256, 256>>>(Wt, Wp);
    gemm_kernel<<<(NN / BM) * (NOUT / BN), GEMM_THREADS, SM_TOTAL>>>();
    gather_max_kernel<<<NN, 128>>>(src, (float*)d_out);
}

// round 5
// speedup vs baseline: 2.8622x; 1.0535x over previous
#include <cuda_runtime.h>
#include <cuda_bf16.h>
#include <cstdint>
#include <cstddef>

#define NN   65536
#define F    512
#define KNN  16
#define NOUT 1024
#define KEXT 1536     // 3 * F : hi*hi, hi*lo, lo*hi

#define BM 128
#define BN 128
#define BK 64
#define STAGES 2
#define GEMM_THREADS 256
#define NKTILES (KEXT / BK)        // 24

// smem row: 64 bf16 data + 8 pad = 72 elems = 144B (16B aligned; ldmatrix
// banks per 8-row group: 4r mod 32 -> conflict-free)
#define ROWE 72
#define ROWB 144
#define TILE_BYTES (128 * ROWB)            // 18432
#define STAGE_BYTES (2 * TILE_BYTES)       // 36864 (A + B)
#define SM_TOTAL (STAGES * STAGE_BYTES)    // 73728

// ---------------- scratch (__device__ globals) ------------------------------
__device__ __align__(1024) float          g_theta[(size_t)NN * F];   // 128MB
__device__ __align__(1024) float          g_phi[(size_t)NN * F];     // 128MB
__device__ __align__(1024) __nv_bfloat16  g_Ahi[(size_t)NN * F];     // 64MB
__device__ __align__(1024) __nv_bfloat16  g_Alo[(size_t)NN * F];     // 64MB
__device__ __align__(1024) __nv_bfloat16  g_BT[(size_t)NOUT * KEXT]; // 3MB
__device__ int g_idx_is64;

// ---------------- helpers ----------------------------------------------------
__device__ __forceinline__ uint32_t smem_to_u32(const void* p) {
    uint32_t a;
    asm("{ .reg .u64 t; cvta.to.shared.u64 t, %1; cvt.u32.u64 %0, t; }"
        : "=r"(a) : "l"(p));
    return a;
}
__device__ __forceinline__ void cp16(uint32_t dst, const void* src) {
    asm volatile("cp.async.cg.shared.global [%0], [%1], 16;" :: "r"(dst), "l"(src));
}
__device__ __forceinline__ void ldmatrix_x4(uint32_t* r, uint32_t addr) {
    asm volatile("ldmatrix.sync.aligned.m8n8.x4.shared.b16 {%0,%1,%2,%3}, [%4];"
                 : "=r"(r[0]), "=r"(r[1]), "=r"(r[2]), "=r"(r[3]) : "r"(addr));
}
__device__ __forceinline__ void mma_bf16(float* c, const uint32_t* a, const uint32_t* b) {
    asm volatile(
        "mma.sync.aligned.m16n8k16.row.col.f32.bf16.bf16.f32 "
        "{%0,%1,%2,%3}, {%4,%5,%6,%7}, {%8,%9}, {%0,%1,%2,%3};"
        : "+f"(c[0]), "+f"(c[1]), "+f"(c[2]), "+f"(c[3])
        : "r"(a[0]), "r"(a[1]), "r"(a[2]), "r"(a[3]), "r"(b[0]), "r"(b[1]));
}

// ---------------- index width detection --------------------------------------
__global__ void detect_idx_kernel(const unsigned int* __restrict__ w) {
    int is64 = 1;
    for (int i = 1; i < 512; i += 2)
        if (w[i] != 0u) { is64 = 0; break; }
    g_idx_is64 = is64;
}

// ---------------- feat -> (hi, lo) bf16 split ---------------------------------
__global__ __launch_bounds__(256) void convert_A_kernel(const float* __restrict__ A) {
    const size_t i = (size_t)blockIdx.x * 256 + threadIdx.x;
    const float4 v = reinterpret_cast<const float4*>(A)[i];
    float f[4] = {v.x, v.y, v.z, v.w};
    __nv_bfloat16 h[4], l[4];
#pragma unroll
    for (int j = 0; j < 4; j++) {
        h[j] = __float2bfloat16_rn(f[j]);
        l[j] = __float2bfloat16_rn(f[j] - __bfloat162float(h[j]));
    }
    reinterpret_cast<uint2*>(g_Ahi)[i] = *reinterpret_cast<uint2*>(h);
    reinterpret_cast<uint2*>(g_Alo)[i] = *reinterpret_cast<uint2*>(l);
}

// ---------------- W -> B_ext^T [NOUT][KEXT] bf16 ------------------------------
__global__ __launch_bounds__(256) void convert_W_kernel(const float* __restrict__ Wt,
                                                        const float* __restrict__ Wp) {
    const int idx = blockIdx.x * 256 + threadIdx.x;
    const int n = idx >> 9;
    const int k = idx & 511;
    const float* W = (n < 512) ? Wt : Wp;
    const int nc = n & 511;
    const float w = W[(size_t)k * 512 + nc];
    const __nv_bfloat16 hi = __float2bfloat16_rn(w);
    const __nv_bfloat16 lo = __float2bfloat16_rn(w - __bfloat162float(hi));
    __nv_bfloat16* row = g_BT + (size_t)n * KEXT;
    row[k]        = hi;
    row[512 + k]  = lo;
    row[1024 + k] = hi;
}

// ---------------- HMMA dual GEMM ----------------------------------------------
__device__ __forceinline__ void load_tile(uint32_t sm_base, int stage, int t,
                                          int m0, int n0, int tid) {
    const int kc = t * BK;
    const __nv_bfloat16* abase = (kc < 1024) ? g_Ahi : g_Alo;
    const int klocal = kc & 511;
    const uint32_t smA = sm_base + stage * STAGE_BYTES;
    const uint32_t smB = smA + TILE_BYTES;
#pragma unroll
    for (int i = 0; i < 4; i++) {
        const int q = tid + i * GEMM_THREADS;   // 0..1023
        const int r = q >> 3;                   // row 0..127
        const int c = q & 7;                    // 16B chunk 0..7
        cp16(smA + r * ROWB + c * 16,
             abase + (size_t)(m0 + r) * F + klocal + c * 8);
    }
#pragma unroll
    for (int i = 0; i < 4; i++) {
        const int q = tid + i * GEMM_THREADS;
        const int r = q >> 3;
        const int c = q & 7;
        cp16(smB + r * ROWB + c * 16,
             g_BT + (size_t)(n0 + r) * KEXT + kc + c * 8);
    }
    asm volatile("cp.async.commit_group;" ::: "memory");
}

__global__ __launch_bounds__(GEMM_THREADS, 2) void gemm_kernel() {
    extern __shared__ __align__(128) char smem[];
    const uint32_t sm_base = smem_to_u32(smem);
    const int tid = threadIdx.x;
    const int wid = tid >> 5;
    const int lid = tid & 31;

    // block swizzle: groups of 32 m-blocks sweep all 8 n-blocks
    const int bid   = blockIdx.x;
    const int group = bid >> 8;
    const int inner = bid & 255;
    const int n_blk = inner >> 5;
    const int m_blk = (group << 5) | (inner & 31);
    const int m0 = m_blk * BM;
    const int n0 = n_blk * BN;

    // warp layout: 4 (m) x 2 (n); warp tile 32m x 64n
    const int wm0 = (wid >> 1) * 32;
    const int wn0 = (wid & 1) * 64;

    float acc[2][8][4];
#pragma unroll
    for (int i = 0; i < 2; i++)
#pragma unroll
        for (int j = 0; j < 8; j++)
#pragma unroll
            for (int q = 0; q < 4; q++) acc[i][j][q] = 0.f;

    load_tile(sm_base, 0, 0, m0, n0, tid);
    load_tile(sm_base, 1, 1, m0, n0, tid);

    const int a_row_off = wm0 + (lid & 15);
    const int a_col_off = (lid >> 4) * 8;
    const int b_row_off = wn0 + ((lid & 16) >> 1) + (lid & 7);
    const int b_col_off = ((lid & 8) ? 8 : 0);

    for (int t = 0; t < NKTILES; t++) {
        const int st = t & 1;
        if (t + 1 < NKTILES) asm volatile("cp.async.wait_group 1;" ::: "memory");
        else                 asm volatile("cp.async.wait_group 0;" ::: "memory");
        __syncthreads();

        const uint32_t smA = sm_base + st * STAGE_BYTES;
        const uint32_t smB = smA + TILE_BYTES;

        // fragment double buffer over 4 ks steps
        uint32_t a[2][2][4], b[2][8][2];
        {
#pragma unroll
            for (int i = 0; i < 2; i++)
                ldmatrix_x4(a[0][i], smA + (a_row_off + i * 16) * ROWB
                                         + a_col_off * 2);
#pragma unroll
            for (int j2 = 0; j2 < 4; j2++) {
                uint32_t r[4];
                ldmatrix_x4(r, smB + (b_row_off + j2 * 16) * ROWB
                                   + b_col_off * 2);
                b[0][j2 * 2 + 0][0] = r[0]; b[0][j2 * 2 + 0][1] = r[1];
                b[0][j2 * 2 + 1][0] = r[2]; b[0][j2 * 2 + 1][1] = r[3];
            }
        }
#pragma unroll
        for (int ks = 0; ks < 4; ks++) {
            const int cur = ks & 1;
            if (ks < 3) {
                const int nxt = cur ^ 1;
                const int col = (ks + 1) * 16;
#pragma unroll
                for (int i = 0; i < 2; i++)
                    ldmatrix_x4(a[nxt][i], smA + (a_row_off + i * 16) * ROWB
                                               + (col + a_col_off) * 2);
#pragma unroll
                for (int j2 = 0; j2 < 4; j2++) {
                    uint32_t r[4];
                    ldmatrix_x4(r, smB + (b_row_off + j2 * 16) * ROWB
                                       + (col + b_col_off) * 2);
                    b[nxt][j2 * 2 + 0][0] = r[0]; b[nxt][j2 * 2 + 0][1] = r[1];
                    b[nxt][j2 * 2 + 1][0] = r[2]; b[nxt][j2 * 2 + 1][1] = r[3];
                }
            }
#pragma unroll
            for (int i = 0; i < 2; i++)
#pragma unroll
                for (int j = 0; j < 8; j++)
                    mma_bf16(acc[i][j], a[cur][i], b[cur][j]);
        }

        // all warps done reading stage st before overwriting it
        __syncthreads();
        if (t + 2 < NKTILES)
            load_tile(sm_base, st, t + 2, m0, n0, tid);
    }

    // epilogue -> compact theta / phi arrays
    float* outbase = (n0 < 512) ? g_theta : g_phi;
    const int nc0 = n0 & 511;
    const int er = lid >> 2;
    const int ec = (lid & 3) * 2;
#pragma unroll
    for (int i = 0; i < 2; i++) {
#pragma unroll
        for (int j = 0; j < 8; j++) {
            const int m = m0 + wm0 + i * 16 + er;
            const int n = nc0 + wn0 + j * 8 + ec;
            float2 v0 = make_float2(acc[i][j][0], acc[i][j][1]);
            float2 v1 = make_float2(acc[i][j][2], acc[i][j][3]);
            *reinterpret_cast<float2*>(&outbase[(size_t)m * F + n])       = v0;
            *reinterpret_cast<float2*>(&outbase[(size_t)(m + 8) * F + n]) = v1;
        }
    }
}

// ---------------- gather + max + add -------------------------------------------
// out[n][c] = max_j theta[src[n][j]][c] + phi[n][c] - theta[n][c]
__global__ __launch_bounds__(128) void gather_max_kernel(
    const void* __restrict__ src, float* __restrict__ out)
{
    const int n  = blockIdx.x;
    const int c4 = threadIdx.x;            // 0..127 float4 lanes

    __shared__ unsigned int sidx[KNN];
    if (threadIdx.x < KNN) {
        if (g_idx_is64) {
            sidx[threadIdx.x] = (unsigned int)((const unsigned long long*)src)
                                    [(size_t)n * KNN + threadIdx.x] & 0xFFFFu;
        } else {
            sidx[threadIdx.x] = ((const unsigned int*)src)
                                    [(size_t)n * KNN + threadIdx.x] & 0xFFFFu;
        }
    }
    __syncthreads();

    const float4* __restrict__ t4 = reinterpret_cast<const float4*>(g_theta);
    const float4* __restrict__ p4 = reinterpret_cast<const float4*>(g_phi);

    float4 m = t4[(size_t)sidx[0] * (F / 4) + c4];
#pragma unroll
    for (int j = 1; j < KNN; j++) {
        const float4 v = t4[(size_t)sidx[j] * (F / 4) + c4];
        m.x = fmaxf(m.x, v.x); m.y = fmaxf(m.y, v.y);
        m.z = fmaxf(m.z, v.z); m.w = fmaxf(m.w, v.w);
    }
    const float4 th = t4[(size_t)n * (F / 4) + c4];
    const float4 ph = p4[(size_t)n * (F / 4) + c4];
    float4 r;
    r.x = m.x + ph.x - th.x; r.y = m.y + ph.y - th.y;
    r.z = m.z + ph.z - th.z; r.w = m.w + ph.w - th.w;
    reinterpret_cast<float4*>(out)[(size_t)n * (F / 4) + c4] = r;
}

// ---------------------------------------------------------------------------------
extern "C" void kernel_launch(void* const* d_in, const int* in_sizes, int n_in,
                              void* d_out, int out_size)
{
    const void*  src  = nullptr;
    const float* feat = nullptr;
    const float* Wt   = nullptr;
    const float* Wp   = nullptr;

    for (int i = 0; i < n_in; i++) {
        const int s = in_sizes[i];
        if (s == NN * KNN)      src  = d_in[i];
        else if (s == NN * F)   feat = (const float*)d_in[i];
        else if (s == F * F) {
            if (!Wt) Wt = (const float*)d_in[i];
            else     Wp = (const float*)d_in[i];
        }
    }

    cudaFuncSetAttribute(gemm_kernel,
                         cudaFuncAttributeMaxDynamicSharedMemorySize, SM_TOTAL);

    detect_idx_kernel<<<1, 1>>>((const unsigned int*)src);
    convert_A_kernel<<<(NN * (F / 4)) / 256, 256>>>(feat);
    convert_W_kernel<<<(NOUT * F) / 256, 256>>>(Wt, Wp);
    gemm_kernel<<<(NN / BM) * (NOUT / BN), GEMM_THREADS, SM_TOTAL>>>();
    gather_max_kernel<<<NN, 128>>>(src, (float*)d_out);
}

// round 6
// speedup vs baseline: 3.1364x; 1.0958x over previous
#include <cuda_runtime.h>
#include <cuda_bf16.h>
#include <cuda_fp16.h>
#include <cstdint>
#include <cstddef>

#define NN   65536
#define F    512
#define KNN  16
#define NOUT 1024
#define KEXT 1536     // 3 * F : hi*hi, hi*lo, lo*hi

#define BM 128
#define BN 128
#define BK 64
#define STAGES 3
#define GEMM_THREADS 256
#define NKTILES (KEXT / BK)        // 24

// smem row: 64 bf16 data + 8 pad = 72 elems = 144B
#define ROWB 144
#define TILE_BYTES (128 * ROWB)            // 18432
#define STAGE_BYTES (2 * TILE_BYTES)       // 36864 (A + B)
#define SM_TOTAL (STAGES * STAGE_BYTES)    // 110592

// ---------------- scratch (__device__ globals) ------------------------------
__device__ __align__(1024) float          g_theta[(size_t)NN * F];    // 128MB
__device__ __align__(1024) float          g_phi[(size_t)NN * F];      // 128MB
__device__ __align__(1024) __half         g_theta16[(size_t)NN * F];  // 64MB
__device__ __align__(1024) __nv_bfloat16  g_Ahi[(size_t)NN * F];      // 64MB
__device__ __align__(1024) __nv_bfloat16  g_Alo[(size_t)NN * F];      // 64MB
__device__ __align__(1024) __nv_bfloat16  g_BT[(size_t)NOUT * KEXT];  // 3MB
__device__ int g_idx_is64;

// ---------------- helpers ----------------------------------------------------
__device__ __forceinline__ uint32_t smem_to_u32(const void* p) {
    uint32_t a;
    asm("{ .reg .u64 t; cvta.to.shared.u64 t, %1; cvt.u32.u64 %0, t; }"
        : "=r"(a) : "l"(p));
    return a;
}
__device__ __forceinline__ void cp16(uint32_t dst, const void* src) {
    asm volatile("cp.async.cg.shared.global [%0], [%1], 16;" :: "r"(dst), "l"(src));
}
__device__ __forceinline__ void ldmatrix_x4(uint32_t* r, uint32_t addr) {
    asm volatile("ldmatrix.sync.aligned.m8n8.x4.shared.b16 {%0,%1,%2,%3}, [%4];"
                 : "=r"(r[0]), "=r"(r[1]), "=r"(r[2]), "=r"(r[3]) : "r"(addr));
}
__device__ __forceinline__ void mma_bf16(float* c, const uint32_t* a, const uint32_t* b) {
    asm volatile(
        "mma.sync.aligned.m16n8k16.row.col.f32.bf16.bf16.f32 "
        "{%0,%1,%2,%3}, {%4,%5,%6,%7}, {%8,%9}, {%0,%1,%2,%3};"
        : "+f"(c[0]), "+f"(c[1]), "+f"(c[2]), "+f"(c[3])
        : "r"(a[0]), "r"(a[1]), "r"(a[2]), "r"(a[3]), "r"(b[0]), "r"(b[1]));
}

// ---------------- index width detection --------------------------------------
__global__ void detect_idx_kernel(const unsigned int* __restrict__ w) {
    int is64 = 1;
    for (int i = 1; i < 512; i += 2)
        if (w[i] != 0u) { is64 = 0; break; }
    g_idx_is64 = is64;
}

// ---------------- feat -> (hi, lo) bf16 split ---------------------------------
__global__ __launch_bounds__(256) void convert_A_kernel(const float* __restrict__ A) {
    const size_t i = (size_t)blockIdx.x * 256 + threadIdx.x;
    const float4 v = reinterpret_cast<const float4*>(A)[i];
    float f[4] = {v.x, v.y, v.z, v.w};
    __nv_bfloat16 h[4], l[4];
#pragma unroll
    for (int j = 0; j < 4; j++) {
        h[j] = __float2bfloat16_rn(f[j]);
        l[j] = __float2bfloat16_rn(f[j] - __bfloat162float(h[j]));
    }
    reinterpret_cast<uint2*>(g_Ahi)[i] = *reinterpret_cast<uint2*>(h);
    reinterpret_cast<uint2*>(g_Alo)[i] = *reinterpret_cast<uint2*>(l);
}

// ---------------- W -> B_ext^T [NOUT][KEXT] bf16 ------------------------------
__global__ __launch_bounds__(256) void convert_W_kernel(const float* __restrict__ Wt,
                                                        const float* __restrict__ Wp) {
    const int idx = blockIdx.x * 256 + threadIdx.x;
    const int n = idx >> 9;
    const int k = idx & 511;
    const float* W = (n < 512) ? Wt : Wp;
    const int nc = n & 511;
    const float w = W[(size_t)k * 512 + nc];
    const __nv_bfloat16 hi = __float2bfloat16_rn(w);
    const __nv_bfloat16 lo = __float2bfloat16_rn(w - __bfloat162float(hi));
    __nv_bfloat16* row = g_BT + (size_t)n * KEXT;
    row[k]        = hi;
    row[512 + k]  = lo;
    row[1024 + k] = hi;
}

// ---------------- HMMA dual GEMM ----------------------------------------------
__device__ __forceinline__ void load_tile(uint32_t sm_base, int stage, int t,
                                          int m0, int n0, int tid) {
    const int kc = t * BK;
    const __nv_bfloat16* abase = (kc < 1024) ? g_Ahi : g_Alo;
    const int klocal = kc & 511;
    const uint32_t smA = sm_base + stage * STAGE_BYTES;
    const uint32_t smB = smA + TILE_BYTES;
#pragma unroll
    for (int i = 0; i < 4; i++) {
        const int q = tid + i * GEMM_THREADS;   // 0..1023
        const int r = q >> 3;
        const int c = q & 7;
        cp16(smA + r * ROWB + c * 16,
             abase + (size_t)(m0 + r) * F + klocal + c * 8);
    }
#pragma unroll
    for (int i = 0; i < 4; i++) {
        const int q = tid + i * GEMM_THREADS;
        const int r = q >> 3;
        const int c = q & 7;
        cp16(smB + r * ROWB + c * 16,
             g_BT + (size_t)(n0 + r) * KEXT + kc + c * 8);
    }
    asm volatile("cp.async.commit_group;" ::: "memory");
}

__global__ __launch_bounds__(GEMM_THREADS, 2) void gemm_kernel() {
    extern __shared__ __align__(128) char smem[];
    const uint32_t sm_base = smem_to_u32(smem);
    const int tid = threadIdx.x;
    const int wid = tid >> 5;
    const int lid = tid & 31;

    // block swizzle: groups of 32 m-blocks sweep all 8 n-blocks
    const int bid   = blockIdx.x;
    const int group = bid >> 8;
    const int inner = bid & 255;
    const int n_blk = inner >> 5;
    const int m_blk = (group << 5) | (inner & 31);
    const int m0 = m_blk * BM;
    const int n0 = n_blk * BN;

    // warp layout: 4 (m) x 2 (n); warp tile 32m x 64n
    const int wm0 = (wid >> 1) * 32;
    const int wn0 = (wid & 1) * 64;

    float acc[2][8][4];
#pragma unroll
    for (int i = 0; i < 2; i++)
#pragma unroll
        for (int j = 0; j < 8; j++)
#pragma unroll
            for (int q = 0; q < 4; q++) acc[i][j][q] = 0.f;

    load_tile(sm_base, 0, 0, m0, n0, tid);
    load_tile(sm_base, 1, 1, m0, n0, tid);

    const int a_row_off = wm0 + (lid & 15);
    const int a_col_off = (lid >> 4) * 8;
    const int b_row_off = wn0 + ((lid & 16) >> 1) + (lid & 7);
    const int b_col_off = ((lid & 8) ? 8 : 0);

    int st = 0;
    for (int t = 0; t < NKTILES; t++) {
        if (t + 1 < NKTILES) asm volatile("cp.async.wait_group 1;" ::: "memory");
        else                 asm volatile("cp.async.wait_group 0;" ::: "memory");
        // one barrier: tile t data visible to all; all warps finished t-1,
        // so slot (t+2)%3 == (t-1)%3 is free to overwrite.
        __syncthreads();

        if (t + 2 < NKTILES) {
            int slot = st + 2; if (slot >= STAGES) slot -= STAGES;
            load_tile(sm_base, slot, t + 2, m0, n0, tid);
        }

        const uint32_t smA = sm_base + st * STAGE_BYTES;
        const uint32_t smB = smA + TILE_BYTES;

        // fragment double buffer over 4 ks steps
        uint32_t a[2][2][4], b[2][8][2];
        {
#pragma unroll
            for (int i = 0; i < 2; i++)
                ldmatrix_x4(a[0][i], smA + (a_row_off + i * 16) * ROWB
                                         + a_col_off * 2);
#pragma unroll
            for (int j2 = 0; j2 < 4; j2++) {
                uint32_t r[4];
                ldmatrix_x4(r, smB + (b_row_off + j2 * 16) * ROWB
                                   + b_col_off * 2);
                b[0][j2 * 2 + 0][0] = r[0]; b[0][j2 * 2 + 0][1] = r[1];
                b[0][j2 * 2 + 1][0] = r[2]; b[0][j2 * 2 + 1][1] = r[3];
            }
        }
#pragma unroll
        for (int ks = 0; ks < 4; ks++) {
            const int cur = ks & 1;
            if (ks < 3) {
                const int nxt = cur ^ 1;
                const int col = (ks + 1) * 16;
#pragma unroll
                for (int i = 0; i < 2; i++)
                    ldmatrix_x4(a[nxt][i], smA + (a_row_off + i * 16) * ROWB
                                               + (col + a_col_off) * 2);
#pragma unroll
                for (int j2 = 0; j2 < 4; j2++) {
                    uint32_t r[4];
                    ldmatrix_x4(r, smB + (b_row_off + j2 * 16) * ROWB
                                       + (col + b_col_off) * 2);
                    b[nxt][j2 * 2 + 0][0] = r[0]; b[nxt][j2 * 2 + 0][1] = r[1];
                    b[nxt][j2 * 2 + 1][0] = r[2]; b[nxt][j2 * 2 + 1][1] = r[3];
                }
            }
#pragma unroll
            for (int i = 0; i < 2; i++)
#pragma unroll
                for (int j = 0; j < 8; j++)
                    mma_bf16(acc[i][j], a[cur][i], b[cur][j]);
        }

        if (++st == STAGES) st = 0;
    }

    // epilogue -> compact theta / phi arrays (+ fp16 theta mirror for gather)
    const bool is_theta = (n0 < 512);
    float* outbase = is_theta ? g_theta : g_phi;
    const int nc0 = n0 & 511;
    const int er = lid >> 2;
    const int ec = (lid & 3) * 2;
#pragma unroll
    for (int i = 0; i < 2; i++) {
#pragma unroll
        for (int j = 0; j < 8; j++) {
            const int m = m0 + wm0 + i * 16 + er;
            const int n = nc0 + wn0 + j * 8 + ec;
            float2 v0 = make_float2(acc[i][j][0], acc[i][j][1]);
            float2 v1 = make_float2(acc[i][j][2], acc[i][j][3]);
            *reinterpret_cast<float2*>(&outbase[(size_t)m * F + n])       = v0;
            *reinterpret_cast<float2*>(&outbase[(size_t)(m + 8) * F + n]) = v1;
            if (is_theta) {
                *reinterpret_cast<__half2*>(&g_theta16[(size_t)m * F + n]) =
                    __float22half2_rn(v0);
                *reinterpret_cast<__half2*>(&g_theta16[(size_t)(m + 8) * F + n]) =
                    __float22half2_rn(v1);
            }
        }
    }
}

// ---------------- gather + max + add -------------------------------------------
// out[n][c] = max_j theta16[src[n][j]][c] + phi[n][c] - theta[n][c]
__global__ __launch_bounds__(128) void gather_max_kernel(
    const void* __restrict__ src, float* __restrict__ out)
{
    const int n  = blockIdx.x;
    const int c4 = threadIdx.x;            // 0..127: 4 features each

    __shared__ unsigned int sidx[KNN];
    if (threadIdx.x < KNN) {
        if (g_idx_is64) {
            sidx[threadIdx.x] = (unsigned int)((const unsigned long long*)src)
                                    [(size_t)n * KNN + threadIdx.x] & 0xFFFFu;
        } else {
            sidx[threadIdx.x] = ((const unsigned int*)src)
                                    [(size_t)n * KNN + threadIdx.x] & 0xFFFFu;
        }
    }
    __syncthreads();

    // gathered reads: fp16, 8B per thread per neighbor
    const uint2* __restrict__ t16 = reinterpret_cast<const uint2*>(g_theta16);

    uint2 raw = t16[(size_t)sidx[0] * (F / 4) + c4];
    __half2 m0 = *reinterpret_cast<__half2*>(&raw.x);
    __half2 m1 = *reinterpret_cast<__half2*>(&raw.y);
#pragma unroll
    for (int j = 1; j < KNN; j++) {
        uint2 r = t16[(size_t)sidx[j] * (F / 4) + c4];
        m0 = __hmax2(m0, *reinterpret_cast<__half2*>(&r.x));
        m1 = __hmax2(m1, *reinterpret_cast<__half2*>(&r.y));
    }

    const float4* __restrict__ t4 = reinterpret_cast<const float4*>(g_theta);
    const float4* __restrict__ p4 = reinterpret_cast<const float4*>(g_phi);
    const float4 th = t4[(size_t)n * (F / 4) + c4];
    const float4 ph = p4[(size_t)n * (F / 4) + c4];

    const float2 f0 = __half22float2(m0);
    const float2 f1 = __half22float2(m1);
    float4 r;
    r.x = f0.x + ph.x - th.x; r.y = f0.y + ph.y - th.y;
    r.z = f1.x + ph.z - th.z; r.w = f1.y + ph.w - th.w;
    reinterpret_cast<float4*>(out)[(size_t)n * (F / 4) + c4] = r;
}

// ---------------------------------------------------------------------------------
extern "C" void kernel_launch(void* const* d_in, const int* in_sizes, int n_in,
                              void* d_out, int out_size)
{
    const void*  src  = nullptr;
    const float* feat = nullptr;
    const float* Wt   = nullptr;
    const float* Wp   = nullptr;

    for (int i = 0; i < n_in; i++) {
        const int s = in_sizes[i];
        if (s == NN * KNN)      src  = d_in[i];
        else if (s == NN * F)   feat = (const float*)d_in[i];
        else if (s == F * F) {
            if (!Wt) Wt = (const float*)d_in[i];
            else     Wp = (const float*)d_in[i];
        }
    }

    cudaFuncSetAttribute(gemm_kernel,
                         cudaFuncAttributeMaxDynamicSharedMemorySize, SM_TOTAL);

    detect_idx_kernel<<<1, 1>>>((const unsigned int*)src);
    convert_A_kernel<<<(NN * (F / 4)) / 256, 256>>>(feat);
    convert_W_kernel<<<(NOUT * F) / 256, 256>>>(Wt, Wp);
    gemm_kernel<<<(NN / BM) * (NOUT / BN), GEMM_THREADS, SM_TOTAL>>>();
    gather_max_kernel<<<NN, 128>>>(src, (float*)d_out);
}

// round 7
// speedup vs baseline: 5.8177x; 1.8549x over previous
#include <cuda_runtime.h>
#include <cuda_fp16.h>
#include <cstdint>
#include <cstddef>

#define NN   65536
#define F    512
#define KNN  16
#define NOUT 1024

#define BM 128
#define BN 128
#define BK 64
#define STAGES 3
#define GEMM_THREADS 256
#define NKTILES (F / BK)           // 8

// smem row: 64 fp16 data + 8 pad = 72 elems = 144B
#define ROWB 144
#define TILE_BYTES (128 * ROWB)            // 18432
#define STAGE_BYTES (2 * TILE_BYTES)       // 36864 (A + B)
#define SM_TOTAL (STAGES * STAGE_BYTES)    // 110592

// ---------------- scratch (__device__ globals) ------------------------------
__device__ __align__(1024) float   g_theta[(size_t)NN * F];    // 128MB
__device__ __align__(1024) float   g_phi[(size_t)NN * F];      // 128MB
__device__ __align__(1024) __half  g_theta16[(size_t)NN * F];  // 64MB
__device__ __align__(1024) __half  g_A16[(size_t)NN * F];      // 64MB
__device__ __align__(1024) __half  g_BT16[(size_t)NOUT * F];   // 1MB
__device__ int g_idx_is64;

// ---------------- helpers ----------------------------------------------------
__device__ __forceinline__ uint32_t smem_to_u32(const void* p) {
    uint32_t a;
    asm("{ .reg .u64 t; cvta.to.shared.u64 t, %1; cvt.u32.u64 %0, t; }"
        : "=r"(a) : "l"(p));
    return a;
}
__device__ __forceinline__ void cp16(uint32_t dst, const void* src) {
    asm volatile("cp.async.cg.shared.global [%0], [%1], 16;" :: "r"(dst), "l"(src));
}
__device__ __forceinline__ void ldmatrix_x4(uint32_t* r, uint32_t addr) {
    asm volatile("ldmatrix.sync.aligned.m8n8.x4.shared.b16 {%0,%1,%2,%3}, [%4];"
                 : "=r"(r[0]), "=r"(r[1]), "=r"(r[2]), "=r"(r[3]) : "r"(addr));
}
__device__ __forceinline__ void mma_f16(float* c, const uint32_t* a, const uint32_t* b) {
    asm volatile(
        "mma.sync.aligned.m16n8k16.row.col.f32.f16.f16.f32 "
        "{%0,%1,%2,%3}, {%4,%5,%6,%7}, {%8,%9}, {%0,%1,%2,%3};"
        : "+f"(c[0]), "+f"(c[1]), "+f"(c[2]), "+f"(c[3])
        : "r"(a[0]), "r"(a[1]), "r"(a[2]), "r"(a[3]), "r"(b[0]), "r"(b[1]));
}

// ---------------- index width detection --------------------------------------
__global__ void detect_idx_kernel(const unsigned int* __restrict__ w) {
    int is64 = 1;
    for (int i = 1; i < 512; i += 2)
        if (w[i] != 0u) { is64 = 0; break; }
    g_idx_is64 = is64;
}

// ---------------- feat -> fp16 ------------------------------------------------
__global__ __launch_bounds__(256) void convert_A_kernel(const float* __restrict__ A) {
    const size_t i = (size_t)blockIdx.x * 256 + threadIdx.x;   // per float4
    const float4 v = reinterpret_cast<const float4*>(A)[i];
    __half2 h0 = __floats2half2_rn(v.x, v.y);
    __half2 h1 = __floats2half2_rn(v.z, v.w);
    uint2 packed;
    packed.x = *reinterpret_cast<uint32_t*>(&h0);
    packed.y = *reinterpret_cast<uint32_t*>(&h1);
    reinterpret_cast<uint2*>(g_A16)[i] = packed;
}

// ---------------- W -> B^T [NOUT][F] fp16 -------------------------------------
__global__ __launch_bounds__(256) void convert_W_kernel(const float* __restrict__ Wt,
                                                        const float* __restrict__ Wp) {
    const int idx = blockIdx.x * 256 + threadIdx.x;   // [0, 1024*512)
    const int n = idx >> 9;
    const int k = idx & 511;
    const float* W = (n < 512) ? Wt : Wp;
    const int nc = n & 511;
    g_BT16[(size_t)n * F + k] = __float2half_rn(W[(size_t)k * 512 + nc]);
}

// ---------------- HMMA dual GEMM ----------------------------------------------
// C[65536 x 1024] = A16[65536 x 512] @ B16[512 x 1024]
__device__ __forceinline__ void load_tile(uint32_t sm_base, int stage, int t,
                                          int m0, int n0, int tid) {
    const int kc = t * BK;
    const uint32_t smA = sm_base + stage * STAGE_BYTES;
    const uint32_t smB = smA + TILE_BYTES;
#pragma unroll
    for (int i = 0; i < 4; i++) {
        const int q = tid + i * GEMM_THREADS;   // 0..1023
        const int r = q >> 3;
        const int c = q & 7;
        cp16(smA + r * ROWB + c * 16,
             g_A16 + (size_t)(m0 + r) * F + kc + c * 8);
    }
#pragma unroll
    for (int i = 0; i < 4; i++) {
        const int q = tid + i * GEMM_THREADS;
        const int r = q >> 3;
        const int c = q & 7;
        cp16(smB + r * ROWB + c * 16,
             g_BT16 + (size_t)(n0 + r) * F + kc + c * 8);
    }
    asm volatile("cp.async.commit_group;" ::: "memory");
}

__global__ __launch_bounds__(GEMM_THREADS, 2) void gemm_kernel() {
    extern __shared__ __align__(128) char smem[];
    const uint32_t sm_base = smem_to_u32(smem);
    const int tid = threadIdx.x;
    const int wid = tid >> 5;
    const int lid = tid & 31;

    // block swizzle: groups of 32 m-blocks sweep all 8 n-blocks
    const int bid   = blockIdx.x;
    const int group = bid >> 8;
    const int inner = bid & 255;
    const int n_blk = inner >> 5;
    const int m_blk = (group << 5) | (inner & 31);
    const int m0 = m_blk * BM;
    const int n0 = n_blk * BN;

    // warp layout: 4 (m) x 2 (n); warp tile 32m x 64n
    const int wm0 = (wid >> 1) * 32;
    const int wn0 = (wid & 1) * 64;

    float acc[2][8][4];
#pragma unroll
    for (int i = 0; i < 2; i++)
#pragma unroll
        for (int j = 0; j < 8; j++)
#pragma unroll
            for (int q = 0; q < 4; q++) acc[i][j][q] = 0.f;

    load_tile(sm_base, 0, 0, m0, n0, tid);
    load_tile(sm_base, 1, 1, m0, n0, tid);

    const int a_row_off = wm0 + (lid & 15);
    const int a_col_off = (lid >> 4) * 8;
    const int b_row_off = wn0 + ((lid & 16) >> 1) + (lid & 7);
    const int b_col_off = ((lid & 8) ? 8 : 0);

    int st = 0;
    for (int t = 0; t < NKTILES; t++) {
        if (t + 1 < NKTILES) asm volatile("cp.async.wait_group 1;" ::: "memory");
        else                 asm volatile("cp.async.wait_group 0;" ::: "memory");
        __syncthreads();

        if (t + 2 < NKTILES) {
            int slot = st + 2; if (slot >= STAGES) slot -= STAGES;
            load_tile(sm_base, slot, t + 2, m0, n0, tid);
        }

        const uint32_t smA = sm_base + st * STAGE_BYTES;
        const uint32_t smB = smA + TILE_BYTES;

        uint32_t a[2][2][4], b[2][8][2];
        {
#pragma unroll
            for (int i = 0; i < 2; i++)
                ldmatrix_x4(a[0][i], smA + (a_row_off + i * 16) * ROWB
                                         + a_col_off * 2);
#pragma unroll
            for (int j2 = 0; j2 < 4; j2++) {
                uint32_t r[4];
                ldmatrix_x4(r, smB + (b_row_off + j2 * 16) * ROWB
                                   + b_col_off * 2);
                b[0][j2 * 2 + 0][0] = r[0]; b[0][j2 * 2 + 0][1] = r[1];
                b[0][j2 * 2 + 1][0] = r[2]; b[0][j2 * 2 + 1][1] = r[3];
            }
        }
#pragma unroll
        for (int ks = 0; ks < 4; ks++) {
            const int cur = ks & 1;
            if (ks < 3) {
                const int nxt = cur ^ 1;
                const int col = (ks + 1) * 16;
#pragma unroll
                for (int i = 0; i < 2; i++)
                    ldmatrix_x4(a[nxt][i], smA + (a_row_off + i * 16) * ROWB
                                               + (col + a_col_off) * 2);
#pragma unroll
                for (int j2 = 0; j2 < 4; j2++) {
                    uint32_t r[4];
                    ldmatrix_x4(r, smB + (b_row_off + j2 * 16) * ROWB
                                       + (col + b_col_off) * 2);
                    b[nxt][j2 * 2 + 0][0] = r[0]; b[nxt][j2 * 2 + 0][1] = r[1];
                    b[nxt][j2 * 2 + 1][0] = r[2]; b[nxt][j2 * 2 + 1][1] = r[3];
                }
            }
#pragma unroll
            for (int i = 0; i < 2; i++)
#pragma unroll
                for (int j = 0; j < 8; j++)
                    mma_f16(acc[i][j], a[cur][i], b[cur][j]);
        }

        if (++st == STAGES) st = 0;
    }

    // epilogue -> theta fp32 + fp16 mirror, or phi fp32
    const bool is_theta = (n0 < 512);
    float* outbase = is_theta ? g_theta : g_phi;
    const int nc0 = n0 & 511;
    const int er = lid >> 2;
    const int ec = (lid & 3) * 2;
#pragma unroll
    for (int i = 0; i < 2; i++) {
#pragma unroll
        for (int j = 0; j < 8; j++) {
            const int m = m0 + wm0 + i * 16 + er;
            const int n = nc0 + wn0 + j * 8 + ec;
            float2 v0 = make_float2(acc[i][j][0], acc[i][j][1]);
            float2 v1 = make_float2(acc[i][j][2], acc[i][j][3]);
            *reinterpret_cast<float2*>(&outbase[(size_t)m * F + n])       = v0;
            *reinterpret_cast<float2*>(&outbase[(size_t)(m + 8) * F + n]) = v1;
            if (is_theta) {
                *reinterpret_cast<__half2*>(&g_theta16[(size_t)m * F + n]) =
                    __float22half2_rn(v0);
                *reinterpret_cast<__half2*>(&g_theta16[(size_t)(m + 8) * F + n]) =
                    __float22half2_rn(v1);
            }
        }
    }
}

// ---------------- gather + max + add -------------------------------------------
// out[n][c] = max_j theta16[src[n][j]][c] + phi[n][c] - theta[n][c]
__global__ __launch_bounds__(128) void gather_max_kernel(
    const void* __restrict__ src, float* __restrict__ out)
{
    const int n  = blockIdx.x;
    const int c4 = threadIdx.x;            // 0..127: 4 features each

    __shared__ unsigned int sidx[KNN];
    if (threadIdx.x < KNN) {
        if (g_idx_is64) {
            sidx[threadIdx.x] = (unsigned int)((const unsigned long long*)src)
                                    [(size_t)n * KNN + threadIdx.x] & 0xFFFFu;
        } else {
            sidx[threadIdx.x] = ((const unsigned int*)src)
                                    [(size_t)n * KNN + threadIdx.x] & 0xFFFFu;
        }
    }
    __syncthreads();

    const uint2* __restrict__ t16 = reinterpret_cast<const uint2*>(g_theta16);

    uint2 raw = t16[(size_t)sidx[0] * (F / 4) + c4];
    __half2 m0 = *reinterpret_cast<__half2*>(&raw.x);
    __half2 m1 = *reinterpret_cast<__half2*>(&raw.y);
#pragma unroll
    for (int j = 1; j < KNN; j++) {
        uint2 r = t16[(size_t)sidx[j] * (F / 4) + c4];
        m0 = __hmax2(m0, *reinterpret_cast<__half2*>(&r.x));
        m1 = __hmax2(m1, *reinterpret_cast<__half2*>(&r.y));
    }

    const float4* __restrict__ t4 = reinterpret_cast<const float4*>(g_theta);
    const float4* __restrict__ p4 = reinterpret_cast<const float4*>(g_phi);
    const float4 th = t4[(size_t)n * (F / 4) + c4];
    const float4 ph = p4[(size_t)n * (F / 4) + c4];

    const float2 f0 = __half22float2(m0);
    const float2 f1 = __half22float2(m1);
    float4 r;
    r.x = f0.x + ph.x - th.x; r.y = f0.y + ph.y - th.y;
    r.z = f1.x + ph.z - th.z; r.w = f1.y + ph.w - th.w;
    reinterpret_cast<float4*>(out)[(size_t)n * (F / 4) + c4] = r;
}

// ---------------------------------------------------------------------------------
extern "C" void kernel_launch(void* const* d_in, const int* in_sizes, int n_in,
                              void* d_out, int out_size)
{
    const void*  src  = nullptr;
    const float* feat = nullptr;
    const float* Wt   = nullptr;
    const float* Wp   = nullptr;

    for (int i = 0; i < n_in; i++) {
        const int s = in_sizes[i];
        if (s == NN * KNN)      src  = d_in[i];
        else if (s == NN * F)   feat = (const float*)d_in[i];
        else if (s == F * F) {
            if (!Wt) Wt = (const float*)d_in[i];
            else     Wp = (const float*)d_in[i];
        }
    }

    cudaFuncSetAttribute(gemm_kernel,
                         cudaFuncAttributeMaxDynamicSharedMemorySize, SM_TOTAL);

    detect_idx_kernel<<<1, 1>>>((const unsigned int*)src);
    convert_A_kernel<<<(NN * (F / 4)) / 256, 256>>>(feat);
    convert_W_kernel<<<(NOUT * F) / 256, 256>>>(Wt, Wp);
    gemm_kernel<<<(NN / BM) * (NOUT / BN), GEMM_THREADS, SM_TOTAL>>>();
    gather_max_kernel<<<NN, 128>>>(src, (float*)d_out);
}

// round 8
// speedup vs baseline: 6.6107x; 1.1363x over previous
#include <cuda_runtime.h>
#include <cuda_fp16.h>
#include <cstdint>
#include <cstddef>

#define NN   65536
#define F    512
#define KNN  16
#define NOUT 1024

#define BM 128
#define BN 128
#define BK 64
#define STAGES 3
#define GEMM_THREADS 128           // 4 warps, 2x2, warp tile 64x64
#define NKTILES (F / BK)           // 8

// smem row: 64 fp16 data + 8 pad = 72 elems = 144B
#define ROWB 144
#define TILE_BYTES (128 * ROWB)            // 18432
#define STAGE_BYTES (2 * TILE_BYTES)       // 36864 (A + B)
#define SM_TOTAL (STAGES * STAGE_BYTES)    // 110592

// ---------------- scratch (__device__ globals) ------------------------------
__device__ __align__(1024) float   g_hdst[(size_t)NN * F];     // 128MB  (phi-theta)
__device__ __align__(1024) __half  g_theta16[(size_t)NN * F];  // 64MB
__device__ __align__(1024) __half  g_A16[(size_t)NN * F];      // 64MB
__device__ __align__(1024) __half  g_BT16[(size_t)NOUT * F];   // 1MB
__device__ int g_idx_is64;

// ---------------- helpers ----------------------------------------------------
__device__ __forceinline__ uint32_t smem_to_u32(const void* p) {
    uint32_t a;
    asm("{ .reg .u64 t; cvta.to.shared.u64 t, %1; cvt.u32.u64 %0, t; }"
        : "=r"(a) : "l"(p));
    return a;
}
__device__ __forceinline__ void cp16(uint32_t dst, const void* src) {
    asm volatile("cp.async.cg.shared.global [%0], [%1], 16;" :: "r"(dst), "l"(src));
}
__device__ __forceinline__ void ldmatrix_x4(uint32_t* r, uint32_t addr) {
    asm volatile("ldmatrix.sync.aligned.m8n8.x4.shared.b16 {%0,%1,%2,%3}, [%4];"
                 : "=r"(r[0]), "=r"(r[1]), "=r"(r[2]), "=r"(r[3]) : "r"(addr));
}
__device__ __forceinline__ void mma_f16(float* c, const uint32_t* a, const uint32_t* b) {
    asm volatile(
        "mma.sync.aligned.m16n8k16.row.col.f32.f16.f16.f32 "
        "{%0,%1,%2,%3}, {%4,%5,%6,%7}, {%8,%9}, {%0,%1,%2,%3};"
        : "+f"(c[0]), "+f"(c[1]), "+f"(c[2]), "+f"(c[3])
        : "r"(a[0]), "r"(a[1]), "r"(a[2]), "r"(a[3]), "r"(b[0]), "r"(b[1]));
}

// ---------------- index width detection --------------------------------------
__global__ void detect_idx_kernel(const unsigned int* __restrict__ w) {
    int is64 = 1;
    for (int i = 1; i < 512; i += 2)
        if (w[i] != 0u) { is64 = 0; break; }
    g_idx_is64 = is64;
}

// ---------------- feat -> fp16 ------------------------------------------------
__global__ __launch_bounds__(256) void convert_A_kernel(const float* __restrict__ A) {
    const size_t i = (size_t)blockIdx.x * 256 + threadIdx.x;
    const float4 v = reinterpret_cast<const float4*>(A)[i];
    __half2 h0 = __floats2half2_rn(v.x, v.y);
    __half2 h1 = __floats2half2_rn(v.z, v.w);
    uint2 packed;
    packed.x = *reinterpret_cast<uint32_t*>(&h0);
    packed.y = *reinterpret_cast<uint32_t*>(&h1);
    reinterpret_cast<uint2*>(g_A16)[i] = packed;
}

// ---------------- W -> B^T fp16: rows [0,512)=Wt^T, [512,1024)=(Wp-Wt)^T ------
__global__ __launch_bounds__(256) void convert_W_kernel(const float* __restrict__ Wt,
                                                        const float* __restrict__ Wp) {
    const int idx = blockIdx.x * 256 + threadIdx.x;   // [0, 1024*512)
    const int n = idx >> 9;
    const int k = idx & 511;
    const int nc = n & 511;
    float w;
    if (n < 512) w = Wt[(size_t)k * 512 + nc];
    else         w = Wp[(size_t)k * 512 + nc] - Wt[(size_t)k * 512 + nc];
    g_BT16[(size_t)n * F + k] = __float2half_rn(w);
}

// ---------------- HMMA dual GEMM ----------------------------------------------
// C[65536 x 1024] = A16 @ [Wt | Wp-Wt], fp16 in, fp32 acc
__device__ __forceinline__ void load_tile(uint32_t sm_base, int stage, int t,
                                          int m0, int n0, int tid) {
    const int kc = t * BK;
    const uint32_t smA = sm_base + stage * STAGE_BYTES;
    const uint32_t smB = smA + TILE_BYTES;
#pragma unroll
    for (int i = 0; i < 8; i++) {
        const int q = tid + i * GEMM_THREADS;   // 0..1023
        const int r = q >> 3;
        const int c = q & 7;
        cp16(smA + r * ROWB + c * 16,
             g_A16 + (size_t)(m0 + r) * F + kc + c * 8);
    }
#pragma unroll
    for (int i = 0; i < 8; i++) {
        const int q = tid + i * GEMM_THREADS;
        const int r = q >> 3;
        const int c = q & 7;
        cp16(smB + r * ROWB + c * 16,
             g_BT16 + (size_t)(n0 + r) * F + kc + c * 8);
    }
    asm volatile("cp.async.commit_group;" ::: "memory");
}

__global__ __launch_bounds__(GEMM_THREADS, 2) void gemm_kernel() {
    extern __shared__ __align__(128) char smem[];
    const uint32_t sm_base = smem_to_u32(smem);
    const int tid = threadIdx.x;
    const int wid = tid >> 5;
    const int lid = tid & 31;

    // block swizzle: groups of 32 m-blocks sweep all 8 n-blocks
    const int bid   = blockIdx.x;
    const int group = bid >> 8;
    const int inner = bid & 255;
    const int n_blk = inner >> 5;
    const int m_blk = (group << 5) | (inner & 31);
    const int m0 = m_blk * BM;
    const int n0 = n_blk * BN;

    // warp layout: 2 (m) x 2 (n); warp tile 64m x 64n
    const int wm0 = (wid >> 1) * 64;
    const int wn0 = (wid & 1) * 64;

    float acc[4][8][4];
#pragma unroll
    for (int i = 0; i < 4; i++)
#pragma unroll
        for (int j = 0; j < 8; j++)
#pragma unroll
            for (int q = 0; q < 4; q++) acc[i][j][q] = 0.f;

    load_tile(sm_base, 0, 0, m0, n0, tid);
    load_tile(sm_base, 1, 1, m0, n0, tid);

    const int a_row_off = wm0 + (lid & 15);
    const int a_col_off = (lid >> 4) * 8;
    const int b_row_off = wn0 + ((lid & 16) >> 1) + (lid & 7);
    const int b_col_off = ((lid & 8) ? 8 : 0);

    int st = 0;
    for (int t = 0; t < NKTILES; t++) {
        if (t + 1 < NKTILES) asm volatile("cp.async.wait_group 1;" ::: "memory");
        else                 asm volatile("cp.async.wait_group 0;" ::: "memory");
        __syncthreads();

        if (t + 2 < NKTILES) {
            int slot = st + 2; if (slot >= STAGES) slot -= STAGES;
            load_tile(sm_base, slot, t + 2, m0, n0, tid);
        }

        const uint32_t smA = sm_base + st * STAGE_BYTES;
        const uint32_t smB = smA + TILE_BYTES;

        // fragment double buffer over 4 ks steps
        uint32_t a[2][4][4], b[2][8][2];
        {
#pragma unroll
            for (int i = 0; i < 4; i++)
                ldmatrix_x4(a[0][i], smA + (a_row_off + i * 16) * ROWB
                                         + a_col_off * 2);
#pragma unroll
            for (int j2 = 0; j2 < 4; j2++) {
                uint32_t r[4];
                ldmatrix_x4(r, smB + (b_row_off + j2 * 16) * ROWB
                                   + b_col_off * 2);
                b[0][j2 * 2 + 0][0] = r[0]; b[0][j2 * 2 + 0][1] = r[1];
                b[0][j2 * 2 + 1][0] = r[2]; b[0][j2 * 2 + 1][1] = r[3];
            }
        }
#pragma unroll
        for (int ks = 0; ks < 4; ks++) {
            const int cur = ks & 1;
            if (ks < 3) {
                const int nxt = cur ^ 1;
                const int col = (ks + 1) * 16;
#pragma unroll
                for (int i = 0; i < 4; i++)
                    ldmatrix_x4(a[nxt][i], smA + (a_row_off + i * 16) * ROWB
                                               + (col + a_col_off) * 2);
#pragma unroll
                for (int j2 = 0; j2 < 4; j2++) {
                    uint32_t r[4];
                    ldmatrix_x4(r, smB + (b_row_off + j2 * 16) * ROWB
                                       + (col + b_col_off) * 2);
                    b[nxt][j2 * 2 + 0][0] = r[0]; b[nxt][j2 * 2 + 0][1] = r[1];
                    b[nxt][j2 * 2 + 1][0] = r[2]; b[nxt][j2 * 2 + 1][1] = r[3];
                }
            }
#pragma unroll
            for (int i = 0; i < 4; i++)
#pragma unroll
                for (int j = 0; j < 8; j++)
                    mma_f16(acc[i][j], a[cur][i], b[cur][j]);
        }

        if (++st == STAGES) st = 0;
    }

    // epilogue: theta blocks -> fp16 mirror only; hdst blocks -> fp32
    const bool is_theta = (n0 < 512);
    const int nc0 = n0 & 511;
    const int er = lid >> 2;
    const int ec = (lid & 3) * 2;
#pragma unroll
    for (int i = 0; i < 4; i++) {
#pragma unroll
        for (int j = 0; j < 8; j++) {
            const int m = m0 + wm0 + i * 16 + er;
            const int n = nc0 + wn0 + j * 8 + ec;
            float2 v0 = make_float2(acc[i][j][0], acc[i][j][1]);
            float2 v1 = make_float2(acc[i][j][2], acc[i][j][3]);
            if (is_theta) {
                *reinterpret_cast<__half2*>(&g_theta16[(size_t)m * F + n]) =
                    __float22half2_rn(v0);
                *reinterpret_cast<__half2*>(&g_theta16[(size_t)(m + 8) * F + n]) =
                    __float22half2_rn(v1);
            } else {
                *reinterpret_cast<float2*>(&g_hdst[(size_t)m * F + n])       = v0;
                *reinterpret_cast<float2*>(&g_hdst[(size_t)(m + 8) * F + n]) = v1;
            }
        }
    }
}

// ---------------- gather + max + add -------------------------------------------
// out[n][c] = max_j theta16[src[n][j]][c] + hdst[n][c]
__global__ __launch_bounds__(128) void gather_max_kernel(
    const void* __restrict__ src, float* __restrict__ out)
{
    const int n  = blockIdx.x;
    const int c4 = threadIdx.x;            // 0..127: 4 features each

    __shared__ unsigned int sidx[KNN];
    if (threadIdx.x < KNN) {
        if (g_idx_is64) {
            sidx[threadIdx.x] = (unsigned int)((const unsigned long long*)src)
                                    [(size_t)n * KNN + threadIdx.x] & 0xFFFFu;
        } else {
            sidx[threadIdx.x] = ((const unsigned int*)src)
                                    [(size_t)n * KNN + threadIdx.x] & 0xFFFFu;
        }
    }
    __syncthreads();

    const uint2* __restrict__ t16 = reinterpret_cast<const uint2*>(g_theta16);

    uint2 raw = t16[(size_t)sidx[0] * (F / 4) + c4];
    __half2 m0 = *reinterpret_cast<__half2*>(&raw.x);
    __half2 m1 = *reinterpret_cast<__half2*>(&raw.y);
#pragma unroll
    for (int j = 1; j < KNN; j++) {
        uint2 r = t16[(size_t)sidx[j] * (F / 4) + c4];
        m0 = __hmax2(m0, *reinterpret_cast<__half2*>(&r.x));
        m1 = __hmax2(m1, *reinterpret_cast<__half2*>(&r.y));
    }

    const float4 hd = reinterpret_cast<const float4*>(g_hdst)[(size_t)n * (F / 4) + c4];

    const float2 f0 = __half22float2(m0);
    const float2 f1 = __half22float2(m1);
    float4 r;
    r.x = f0.x + hd.x; r.y = f0.y + hd.y;
    r.z = f1.x + hd.z; r.w = f1.y + hd.w;
    reinterpret_cast<float4*>(out)[(size_t)n * (F / 4) + c4] = r;
}

// ---------------------------------------------------------------------------------
extern "C" void kernel_launch(void* const* d_in, const int* in_sizes, int n_in,
                              void* d_out, int out_size)
{
    const void*  src  = nullptr;
    const float* feat = nullptr;
    const float* Wt   = nullptr;
    const float* Wp   = nullptr;

    for (int i = 0; i < n_in; i++) {
        const int s = in_sizes[i];
        if (s == NN * KNN)      src  = d_in[i];
        else if (s == NN * F)   feat = (const float*)d_in[i];
        else if (s == F * F) {
            if (!Wt) Wt = (const float*)d_in[i];
            else     Wp = (const float*)d_in[i];
        }
    }

    cudaFuncSetAttribute(gemm_kernel,
                         cudaFuncAttributeMaxDynamicSharedMemorySize, SM_TOTAL);

    detect_idx_kernel<<<1, 1>>>((const unsigned int*)src);
    convert_A_kernel<<<(NN * (F / 4)) / 256, 256>>>(feat);
    convert_W_kernel<<<(NOUT * F) / 256, 256>>>(Wt, Wp);
    gemm_kernel<<<(NN / BM) * (NOUT / BN), GEMM_THREADS, SM_TOTAL>>>();
    gather_max_kernel<<<NN, 128>>>(src, (float*)d_out);
}